// round 6
// baseline (speedup 1.0000x reference)
#include <cuda_runtime.h>

// RoI bilinear pooling:
//   feat: (1, H=200, W=200, C=1024) fp32
//   rois: (N=300, 4) int32  [x0, y0, w, h]
//   out : (N, 7, 7, C) fp32
//
// R4 (resubmit after infra failure): one CTA per (roi, py) row = 7 cells,
// fully unrolled with double-buffered prefetch. Each thread keeps 8 LDG.128
// in flight continuously (sustained MLP, not a one-shot burst), y-setup
// amortized over 7 cells, and all loads in a CTA hit the same two feature
// rows (L1/L2 locality).

#define POOL  7
#define FH    200
#define FW    200
#define FC    1024
#define VEC   (FC / 4)     // 256 float4 per pixel row
#define NCELL (POOL * POOL)

__device__ __forceinline__ float4 lerp2d(float4 a, float4 b, float4 g, float4 d,
                                         float wx0, float wx1, float wy0, float wy1)
{
    float4 o;
    o.x = (a.x * wx0 + b.x * wx1) * wy0 + (g.x * wx0 + d.x * wx1) * wy1;
    o.y = (a.y * wx0 + b.y * wx1) * wy0 + (g.y * wx0 + d.y * wx1) * wy1;
    o.z = (a.z * wx0 + b.z * wx1) * wy0 + (g.z * wx0 + d.z * wx1) * wy1;
    o.w = (a.w * wx0 + b.w * wx1) * wy0 + (g.w * wx0 + d.w * wx1) * wy1;
    return o;
}

__global__ __launch_bounds__(VEC)
void roi_pool_row_kernel(const float* __restrict__ feat,
                         const int*   __restrict__ rois,
                         float*       __restrict__ out)
{
    const int py = blockIdx.x;              // 0..6
    const int n  = blockIdx.y;              // roi index

    const int4 r = __ldg(((const int4*)rois) + n);
    const int x0 = r.x, y0 = r.y, w = r.z, h = r.w;

    // ---- y setup (once per 7 cells) ----
    const float ry  = (float)py * ((float)h / (float)POOL);
    const int   ylo = (int)floorf(ry);
    const float fy  = ry - (float)ylo;
    const int   yhi = min(ylo + 1, h - 1);
    const int   iy0 = min(max(y0 + ylo, 0), FH - 1);
    const int   iy1 = min(max(y0 + yhi, 0), FH - 1);
    const float wy1 = fy, wy0 = 1.0f - fy;

    const float* row0 = feat + (size_t)iy0 * FW * FC;
    const float* row1 = feat + (size_t)iy1 * FW * FC;

    // ---- x setup for all 7 cells (registers; loop fully unrolled below) ----
    int   ix0a[POOL], ix1a[POOL];
    float fxa[POOL];
    const float winv = (float)w / (float)POOL;
#pragma unroll
    for (int px = 0; px < POOL; px++) {
        const float rx  = (float)px * winv;
        const int   xlo = (int)floorf(rx);
        fxa[px]         = rx - (float)xlo;
        const int   xhi = min(xlo + 1, w - 1);
        ix0a[px] = min(max(x0 + xlo, 0), FW - 1);
        ix1a[px] = min(max(x0 + xhi, 0), FW - 1);
    }

    const int c = threadIdx.x;              // 0..255 float4 lanes
    float4* outv = (float4*)out;
    const size_t obase = ((size_t)n * NCELL + (size_t)py * POOL) * VEC + c;

    // ---- prefetch cell 0 ----
    float4 ca = __ldg((const float4*)(row0 + (size_t)ix0a[0] * FC) + c);
    float4 cb = __ldg((const float4*)(row0 + (size_t)ix1a[0] * FC) + c);
    float4 cg = __ldg((const float4*)(row1 + (size_t)ix0a[0] * FC) + c);
    float4 cd = __ldg((const float4*)(row1 + (size_t)ix1a[0] * FC) + c);

#pragma unroll
    for (int px = 0; px < POOL; px++) {
        float4 na, nb, ng, nd;
        if (px + 1 < POOL) {
            // issue next cell's loads before consuming current cell's data
            na = __ldg((const float4*)(row0 + (size_t)ix0a[px + 1] * FC) + c);
            nb = __ldg((const float4*)(row0 + (size_t)ix1a[px + 1] * FC) + c);
            ng = __ldg((const float4*)(row1 + (size_t)ix0a[px + 1] * FC) + c);
            nd = __ldg((const float4*)(row1 + (size_t)ix1a[px + 1] * FC) + c);
        }

        const float wx1 = fxa[px], wx0 = 1.0f - fxa[px];
        outv[obase + (size_t)px * VEC] =
            lerp2d(ca, cb, cg, cd, wx0, wx1, wy0, wy1);

        if (px + 1 < POOL) { ca = na; cb = nb; cg = ng; cd = nd; }
    }
}

extern "C" void kernel_launch(void* const* d_in, const int* in_sizes, int n_in,
                              void* d_out, int out_size)
{
    const float* feat = (const float*)d_in[0];   // (1,200,200,1024) fp32
    const int*   rois = (const int*)d_in[1];     // (N,4) int32
    const int N = in_sizes[1] / 4;

    dim3 grid(POOL, N);
    roi_pool_row_kernel<<<grid, VEC>>>(feat, rois, (float*)d_out);
}

// round 7
// speedup vs baseline: 1.0956x; 1.0956x over previous
#include <cuda_runtime.h>

// RoI bilinear pooling:
//   feat: (1, H=200, W=200, C=1024) fp32
//   rois: (N=300, 4) int32  [x0, y0, w, h]
//   out : (N, 7, 7, C) fp32
//
// R7: champion R2 structure (2 cells/CTA, 7500 CTAs, burst-8 loads) with
//   (a) __launch_bounds__(256, 6): allow ~42 regs so ptxas can keep all 8
//       float4 loads truly in flight (at 31 regs it serialized the burst),
//   (b) __stcs streaming stores: output is write-once, keep it from
//       evicting feat lines in L2.

#define POOL  7
#define FH    200
#define FW    200
#define FC    1024
#define VEC   (FC / 4)     // 256 float4 per pixel row
#define NCELL (POOL * POOL)
#define NPAIR ((NCELL + 1) / 2)   // 25

__device__ __forceinline__ void cell_setup(int cell, int x0, int y0, int w, int h,
                                           const float* __restrict__ feat,
                                           const float4** p00, const float4** p01,
                                           const float4** p10, const float4** p11,
                                           float* wx0, float* wx1,
                                           float* wy0, float* wy1)
{
    const int py = cell / POOL;
    const int px = cell - py * POOL;

    const float ry = (float)py * ((float)h / (float)POOL);
    const float rx = (float)px * ((float)w / (float)POOL);
    const int ylo = (int)floorf(ry);
    const int xlo = (int)floorf(rx);
    const float fy = ry - (float)ylo;
    const float fx = rx - (float)xlo;
    const int yhi = min(ylo + 1, h - 1);
    const int xhi = min(xlo + 1, w - 1);

    const int iy0 = min(max(y0 + ylo, 0), FH - 1);
    const int iy1 = min(max(y0 + yhi, 0), FH - 1);
    const int ix0 = min(max(x0 + xlo, 0), FW - 1);
    const int ix1 = min(max(x0 + xhi, 0), FW - 1);

    *wx1 = fx;  *wx0 = 1.0f - fx;
    *wy1 = fy;  *wy0 = 1.0f - fy;

    *p00 = (const float4*)(feat + ((size_t)iy0 * FW + ix0) * FC);
    *p01 = (const float4*)(feat + ((size_t)iy0 * FW + ix1) * FC);
    *p10 = (const float4*)(feat + ((size_t)iy1 * FW + ix0) * FC);
    *p11 = (const float4*)(feat + ((size_t)iy1 * FW + ix1) * FC);
}

__device__ __forceinline__ float4 lerp2d(float4 a, float4 b, float4 g, float4 d,
                                         float wx0, float wx1, float wy0, float wy1)
{
    float4 o;
    o.x = (a.x * wx0 + b.x * wx1) * wy0 + (g.x * wx0 + d.x * wx1) * wy1;
    o.y = (a.y * wx0 + b.y * wx1) * wy0 + (g.y * wx0 + d.y * wx1) * wy1;
    o.z = (a.z * wx0 + b.z * wx1) * wy0 + (g.z * wx0 + d.z * wx1) * wy1;
    o.w = (a.w * wx0 + b.w * wx1) * wy0 + (g.w * wx0 + d.w * wx1) * wy1;
    return o;
}

__global__ __launch_bounds__(VEC, 6)
void roi_pool_kernel(const float* __restrict__ feat,
                     const int*   __restrict__ rois,
                     float*       __restrict__ out)
{
    const int pair = blockIdx.x;            // 0..24
    const int n    = blockIdx.y;            // roi index
    const int cellA = pair * 2;
    const bool hasB = (cellA + 1) < NCELL;
    const int cellB = hasB ? (cellA + 1) : cellA;

    const int4 r = __ldg(((const int4*)rois) + n);
    const int x0 = r.x, y0 = r.y, w = r.z, h = r.w;

    const float4 *a00, *a01, *a10, *a11;
    const float4 *b00, *b01, *b10, *b11;
    float awx0, awx1, awy0, awy1;
    float bwx0, bwx1, bwy0, bwy1;

    cell_setup(cellA, x0, y0, w, h, feat, &a00, &a01, &a10, &a11,
               &awx0, &awx1, &awy0, &awy1);
    cell_setup(cellB, x0, y0, w, h, feat, &b00, &b01, &b10, &b11,
               &bwx0, &bwx1, &bwy0, &bwy1);

    const int c = threadIdx.x;              // 0..255 float4 lanes

    // Burst-issue all 8 loads before any use — true 8-deep MLP per thread
    // (launch_bounds gives ptxas the registers to keep them alive).
    const float4 va = __ldg(a00 + c);
    const float4 vb = __ldg(a01 + c);
    const float4 vg = __ldg(a10 + c);
    const float4 vd = __ldg(a11 + c);
    const float4 ua = __ldg(b00 + c);
    const float4 ub = __ldg(b01 + c);
    const float4 ug = __ldg(b10 + c);
    const float4 ud = __ldg(b11 + c);

    float4* outv = (float4*)out;
    const size_t base = (size_t)n * NCELL;

    // Streaming (evict-first) stores: output is never re-read; keep L2 for feat.
    const float4 oA = lerp2d(va, vb, vg, vd, awx0, awx1, awy0, awy1);
    __stcs(outv + (base + cellA) * VEC + c, oA);

    if (hasB) {
        const float4 oB = lerp2d(ua, ub, ug, ud, bwx0, bwx1, bwy0, bwy1);
        __stcs(outv + (base + cellB) * VEC + c, oB);
    }
}

extern "C" void kernel_launch(void* const* d_in, const int* in_sizes, int n_in,
                              void* d_out, int out_size)
{
    const float* feat = (const float*)d_in[0];   // (1,200,200,1024) fp32
    const int*   rois = (const int*)d_in[1];     // (N,4) int32
    const int N = in_sizes[1] / 4;

    dim3 grid(NPAIR, N);
    roi_pool_kernel<<<grid, VEC>>>(feat, rois, (float*)d_out);
}